// round 12
// baseline (speedup 1.0000x reference)
#include <cuda_runtime.h>
#include <cstdint>

#define DD 1024
#define VV 1024
#define BB 64
#define UU 512
#define TS 513           // U+1 steps
#define G3 3072
#define JJ 1024
#define NCTA 128         // 128 CTAs x 8 j-cols each = 1024 gate-triples

// recurrent smem layout (floats)
#define WS_FLOATS (1024 * 24)            // W slice [k][24 rows]
#define HB_STRIDE 66                     // h chunk row stride (conflict-free)
#define HB_FLOATS (128 * HB_STRIDE)      // one h chunk [128 k][66]
#define H_OFF WS_FLOATS
#define Y_OFF (WS_FLOATS + 2 * HB_FLOATS)
#define SM_FLOATS (Y_OFF + 64)

// ---------------- f32x2 packed-FMA helpers ----------------
__device__ __forceinline__ unsigned long long pack2(float x, float y) {
    unsigned long long r;
    asm("mov.b64 %0, {%1, %2};" : "=l"(r) : "f"(x), "f"(y));
    return r;
}
__device__ __forceinline__ unsigned long long fma2(unsigned long long a,
                                                   unsigned long long b,
                                                   unsigned long long c) {
    unsigned long long d;
    asm("fma.rn.f32x2 %0, %1, %2, %3;" : "=l"(d) : "l"(a), "l"(b), "l"(c));
    return d;
}
__device__ __forceinline__ float2 unpack2(unsigned long long v) {
    float2 f;
    asm("mov.b64 {%0, %1}, %2;" : "=f"(f.x), "=f"(f.y) : "l"(v));
    return f;
}
__device__ __forceinline__ unsigned ld_acq(const unsigned* p) {
    unsigned v;
    asm volatile("ld.global.acquire.gpu.u32 %0, [%1];" : "=r"(v) : "l"(p));
    return v;
}

// ---------------- static device scratch (alloc-free rule) ----------------
__device__ __align__(16) float g_table[(size_t)VV * G3];   // W_ih@embed^T + b_ih
__device__ __align__(16) float g_hs[(size_t)TS * BB * DD]; // all hidden states
__device__ __align__(16) float g_hbuf[2][BB * DD];         // ping-pong hidden state
__device__ unsigned g_grp_cnt[16];                         // per-group step counters
__device__ unsigned g_bar_cnt;
__device__ unsigned g_bar_phase;

// ---------------- software grid barrier (init only) ----------------
__device__ __forceinline__ void gsync(unsigned target) {
    __syncthreads();
    if (threadIdx.x == 0) {
        __threadfence();
        unsigned a = atomicAdd(&g_bar_cnt, 1u);
        if (a == (unsigned)gridDim.x - 1u) {
            *(volatile unsigned*)&g_bar_cnt = 0u;
            __threadfence();
            atomicExch(&g_bar_phase, target);
        } else {
            while (*(volatile unsigned*)&g_bar_phase != target) { }
            __threadfence();
        }
    }
    __syncthreads();
}

// ---------------- fp32 GEMM v4 (double-buffered): C = A.B^T + bias ----------------
// A:[M][1024] K-major, B:[N][1024] K-major. Tile 64x128, 256 thr, f32x2 over n.
// M multiple of 64. remap=1: C-row = (m&63)*TS + (m>>6).
__global__ __launch_bounds__(256, 2) void gemm_nt(
    const float* __restrict__ A, const float* __restrict__ Bm,
    const float* __restrict__ bias, float* __restrict__ C,
    int ldc, int remap)
{
    __shared__ float As[2][16][68];
    __shared__ float Bs[2][16][132];
    const int tid = threadIdx.x;
    const int m0 = blockIdx.y * 64;
    const int n0 = blockIdx.x * 128;
    const int tx = tid & 15;
    const int ty = tid >> 4;
    const int ar = tid >> 2, aq = tid & 3;
    const int br0 = (tid) >> 2, bq0 = tid & 3;
    const int br1 = (tid + 256) >> 2, bq1 = tid & 3;

    unsigned long long acc2[4][4];
#pragma unroll
    for (int i = 0; i < 4; i++)
#pragma unroll
        for (int j = 0; j < 4; j++) acc2[i][j] = 0ull;

    {
        float4 av = *(const float4*)(A + (size_t)(m0 + ar) * 1024 + aq * 4);
        As[0][aq * 4 + 0][ar] = av.x; As[0][aq * 4 + 1][ar] = av.y;
        As[0][aq * 4 + 2][ar] = av.z; As[0][aq * 4 + 3][ar] = av.w;
        float4 b0 = *(const float4*)(Bm + (size_t)(n0 + br0) * 1024 + bq0 * 4);
        Bs[0][bq0 * 4 + 0][br0] = b0.x; Bs[0][bq0 * 4 + 1][br0] = b0.y;
        Bs[0][bq0 * 4 + 2][br0] = b0.z; Bs[0][bq0 * 4 + 3][br0] = b0.w;
        float4 b1 = *(const float4*)(Bm + (size_t)(n0 + br1) * 1024 + bq1 * 4);
        Bs[0][bq1 * 4 + 0][br1] = b1.x; Bs[0][bq1 * 4 + 1][br1] = b1.y;
        Bs[0][bq1 * 4 + 2][br1] = b1.z; Bs[0][bq1 * 4 + 3][br1] = b1.w;
    }
    __syncthreads();

#pragma unroll 1
    for (int it = 0; it < 64; it++) {
        const int cur = it & 1;
        float4 avN, b0N, b1N;
        if (it < 63) {
            const int k0 = (it + 1) * 16;
            avN = *(const float4*)(A + (size_t)(m0 + ar) * 1024 + k0 + aq * 4);
            b0N = *(const float4*)(Bm + (size_t)(n0 + br0) * 1024 + k0 + bq0 * 4);
            b1N = *(const float4*)(Bm + (size_t)(n0 + br1) * 1024 + k0 + bq1 * 4);
        }
#pragma unroll
        for (int kk = 0; kk < 16; kk++) {
            unsigned long long rn2[4];
#pragma unroll
            for (int j = 0; j < 4; j++)
                rn2[j] = *(const unsigned long long*)&Bs[cur][kk][tx * 2 + 32 * j];
#pragma unroll
            for (int i = 0; i < 4; i++) {
                float a = As[cur][kk][ty + 16 * i];
                unsigned long long am = pack2(a, a);
#pragma unroll
                for (int j = 0; j < 4; j++)
                    acc2[i][j] = fma2(am, rn2[j], acc2[i][j]);
            }
        }
        if (it < 63) {
            const int nxt = cur ^ 1;
            As[nxt][aq * 4 + 0][ar] = avN.x; As[nxt][aq * 4 + 1][ar] = avN.y;
            As[nxt][aq * 4 + 2][ar] = avN.z; As[nxt][aq * 4 + 3][ar] = avN.w;
            Bs[nxt][bq0 * 4 + 0][br0] = b0N.x; Bs[nxt][bq0 * 4 + 1][br0] = b0N.y;
            Bs[nxt][bq0 * 4 + 2][br0] = b0N.z; Bs[nxt][bq0 * 4 + 3][br0] = b0N.w;
            Bs[nxt][bq1 * 4 + 0][br1] = b1N.x; Bs[nxt][bq1 * 4 + 1][br1] = b1N.y;
            Bs[nxt][bq1 * 4 + 2][br1] = b1N.z; Bs[nxt][bq1 * 4 + 3][br1] = b1N.w;
            __syncthreads();
        }
    }

    float2 b2[4];
#pragma unroll
    for (int j = 0; j < 4; j++)
        b2[j] = *(const float2*)(bias + n0 + tx * 2 + 32 * j);

#pragma unroll
    for (int i = 0; i < 4; i++) {
        int m = m0 + ty + 16 * i;
        int orow = remap ? ((m & 63) * TS + (m >> 6)) : m;
#pragma unroll
        for (int j = 0; j < 4; j++) {
            float2 v = unpack2(acc2[i][j]);
            float2 o = {v.x + b2[j].x, v.y + b2[j].y};
            *(float2*)(C + (size_t)orow * ldc + n0 + tx * 2 + 32 * j) = o;
        }
    }
}

// ---------------- persistent GRU recurrence v4: flag-synced, barrier-free ----------------
// CTA owns 8 j-cols x 3 gates = 24 full-K W_hh rows in smem (96KB).
// Cross-CTA sync: per-group(16 CTAs) release counters; consumers acquire-poll
// one word per k-chunk, one chunk ahead. No global barrier in the step loop.
__global__ __launch_bounds__(256, 1) void recurrent(
    const float* __restrict__ Whh, const float* __restrict__ bhh,
    const int* __restrict__ y, const float* __restrict__ h0)
{
    extern __shared__ float smem[];
    float* w_s = smem;                       // [1024 k][24 rows]
    int* y_si = (int*)(smem + Y_OFF);

    const int tid = threadIdx.x;
    const int lane = tid & 31;
    const int warp = tid >> 5;
    const int cta = blockIdx.x;
    const int rg = lane >> 3;                // 0..3 -> rows rg*6..+5
    const int bg = lane & 7;                 // 0..7 -> bpairs bg+8jj
    const int hb_b = tid >> 2, hb_fq = tid & 3;   // h loader mapping
    const int c0 = cta >> 4;                 // own chunk/group
    // gate-thread constants
    const int jl = tid & 7;
    const int bb = tid >> 3;
    const int j = cta * 8 + jl;
    const int b0 = 2 * bb, b1 = 2 * bb + 1;

    unsigned target = *(volatile unsigned*)&g_bar_phase;

    // ---- load W slice once: local row rho -> global row (rho/8)*1024 + cta*8 + rho%8
#pragma unroll 4
    for (int p = 0; p < 24; p++) {
        int e = p * 256 + tid;
        int rho = e >> 8;
        int f4 = e & 255;
        int grow = (rho >> 3) * 1024 + cta * 8 + (rho & 7);
        float4 wv = *(const float4*)(Whh + (size_t)grow * DD + f4 * 4);
        w_s[(f4 * 4 + 0) * 24 + rho] = wv.x;
        w_s[(f4 * 4 + 1) * 24 + rho] = wv.y;
        w_s[(f4 * 4 + 2) * 24 + rho] = wv.z;
        w_s[(f4 * 4 + 3) * 24 + rho] = wv.w;
    }

    // reset group counters + broadcast initial_state, then ONE init barrier
    if (cta < 16 && tid == 0) g_grp_cnt[cta] = 0u;
    for (int e = cta * 256 + tid; e < BB * DD; e += NCTA * 256)
        g_hbuf[0][e] = h0[e & (DD - 1)];
    gsync(++target);

    // loop-invariant gate biases
    const float brr = bhh[j], bzz = bhh[DD + j], bnn = bhh[2 * DD + j];

#pragma unroll 1
    for (int t = 0; t < TS; t++) {
        const float* __restrict__ hc = g_hbuf[t & 1];
        float* __restrict__ hn = g_hbuf[(t + 1) & 1];
        const unsigned lim = 16u * (unsigned)t;   // h_t ready when grp cnt >= lim

        // tokens (input-only, overlap with wait)
        if (tid < BB) y_si[tid] = (t == 0) ? 0 : y[tid * UU + t - 1];

        // wait own chunk's producers, then stage chunk c0
        while (ld_acq(&g_grp_cnt[c0]) < lim) { }
        {
            const float* src = hc + hb_b * DD + c0 * 128;
            float4 p0[8];
#pragma unroll
            for (int u = 0; u < 8; u++)
                p0[u] = __ldcg((const float4*)(src + (hb_fq + 4 * u) * 4));
            float* hb = smem + H_OFF;
#pragma unroll
            for (int u = 0; u < 8; u++) {
                int kap = (hb_fq + 4 * u) * 4;
                hb[(kap + 0) * HB_STRIDE + hb_b] = p0[u].x;
                hb[(kap + 1) * HB_STRIDE + hb_b] = p0[u].y;
                hb[(kap + 2) * HB_STRIDE + hb_b] = p0[u].z;
                hb[(kap + 3) * HB_STRIDE + hb_b] = p0[u].w;
            }
        }
        __syncthreads();

        // early prefetch of gate operands (consumed after mainloop)
        const int tok0 = y_si[b0], tok1 = y_si[b1];
        const float* t0p = g_table + (size_t)tok0 * G3;
        const float* t1p = g_table + (size_t)tok1 * G3;
        float p_t0r = __ldcg(t0p + j), p_t0z = __ldcg(t0p + DD + j), p_t0n = __ldcg(t0p + 2 * DD + j);
        float p_t1r = __ldcg(t1p + j), p_t1z = __ldcg(t1p + DD + j), p_t1n = __ldcg(t1p + 2 * DD + j);
        float p_h00 = __ldcg(hc + (size_t)b0 * DD + j);
        float p_h01 = __ldcg(hc + (size_t)b1 * DD + j);

        // ---- mainloop over chunks, rotated to start at own group ----
        unsigned long long acc2[6][4];
#pragma unroll
        for (int i = 0; i < 6; i++)
#pragma unroll
            for (int jj = 0; jj < 4; jj++) acc2[i][jj] = 0ull;

#pragma unroll 1
        for (int ci = 0; ci < 8; ci++) {
            const int c = (c0 + ci) & 7;
            float4 pf[8];
            if (ci < 7) {
                const int cn = (c0 + ci + 1) & 7;
                while (ld_acq(&g_grp_cnt[cn]) < lim) { }
                const float* srcn = hc + hb_b * DD + cn * 128;
#pragma unroll
                for (int u = 0; u < 8; u++)
                    pf[u] = __ldcg((const float4*)(srcn + (hb_fq + 4 * u) * 4));
            }
            const float* hb = smem + H_OFF + (ci & 1) * HB_FLOATS;
            const float* wb = w_s + c * 128 * 24;
#pragma unroll
            for (int kap = 0; kap < 16; kap++) {
                const int kk = warp * 16 + kap;
                unsigned long long rh2[4];
#pragma unroll
                for (int jj = 0; jj < 4; jj++)
                    rh2[jj] = *(const unsigned long long*)&hb[kk * HB_STRIDE + 2 * (bg + 8 * jj)];
#pragma unroll
                for (int i = 0; i < 6; i++) {
                    float wv = wb[kk * 24 + rg * 6 + i];
                    unsigned long long w2 = pack2(wv, wv);
#pragma unroll
                    for (int jj = 0; jj < 4; jj++)
                        acc2[i][jj] = fma2(rh2[jj], w2, acc2[i][jj]);
                }
            }
            if (ci < 7) {
                float* hb2 = smem + H_OFF + ((ci + 1) & 1) * HB_FLOATS;
#pragma unroll
                for (int u = 0; u < 8; u++) {
                    int kap = (hb_fq + 4 * u) * 4;
                    hb2[(kap + 0) * HB_STRIDE + hb_b] = pf[u].x;
                    hb2[(kap + 1) * HB_STRIDE + hb_b] = pf[u].y;
                    hb2[(kap + 2) * HB_STRIDE + hb_b] = pf[u].z;
                    hb2[(kap + 3) * HB_STRIDE + hb_b] = pf[u].w;
                }
                __syncthreads();
            }
        }
        __syncthreads();   // h buffers consumed -> safe to overlay partials

        // ---- per-warp partials -> smem (overlay on h region), stride-33 ull ----
        unsigned long long* redq = (unsigned long long*)(smem + H_OFF);
#pragma unroll
        for (int i = 0; i < 6; i++)
#pragma unroll
            for (int jj = 0; jj < 4; jj++)
                redq[((size_t)warp * 24 + rg * 6 + i) * 33 + bg + 8 * jj] = acc2[i][jj];
        __syncthreads();

        // ---- reduce 8 warps + gates ----
        {
            const float2* red2 = (const float2*)(smem + H_OFF);
            float2 sr = {0.f, 0.f}, sz = {0.f, 0.f}, sn = {0.f, 0.f};
#pragma unroll
            for (int w = 0; w < 8; w++) {
                float2 a = red2[(w * 24 + jl) * 33 + bb];
                float2 b = red2[(w * 24 + 8 + jl) * 33 + bb];
                float2 cpl = red2[(w * 24 + 16 + jl) * 33 + bb];
                sr.x += a.x; sr.y += a.y;
                sz.x += b.x; sz.y += b.y;
                sn.x += cpl.x; sn.y += cpl.y;
            }
            float xr0 = p_t0r + sr.x + brr,      xr1 = p_t1r + sr.y + brr;
            float xz0 = p_t0z + sz.x + bzz,      xz1 = p_t1z + sz.y + bzz;
            float gn0 = sn.x + bnn,              gn1 = sn.y + bnn;
            float r0 = 1.f / (1.f + __expf(-xr0)), r1 = 1.f / (1.f + __expf(-xr1));
            float z0 = 1.f / (1.f + __expf(-xz0)), z1 = 1.f / (1.f + __expf(-xz1));
            float n0 = tanhf(p_t0n + r0 * gn0),    n1 = tanhf(p_t1n + r1 * gn1);
            float hv0 = (1.f - z0) * n0 + z0 * p_h00;
            float hv1 = (1.f - z1) * n1 + z1 * p_h01;
            hn[(size_t)b0 * DD + j] = hv0;
            hn[(size_t)b1 * DD + j] = hv1;
            g_hs[((size_t)t * BB + b0) * DD + j] = hv0;
            g_hs[((size_t)t * BB + b1) * DD + j] = hv1;
        }
        // publish: all writes done -> release group counter
        __syncthreads();
        if (tid == 0) {
            __threadfence();
            atomicAdd(&g_grp_cnt[c0], 1u);
        }
    }
}

// ---------------- launch ----------------
extern "C" void kernel_launch(void* const* d_in, const int* in_sizes, int n_in,
                              void* d_out, int out_size) {
    const int*   y     = (const int*)d_in[0];
    const float* embed = (const float*)d_in[1];
    const float* wih   = (const float*)d_in[2];
    const float* bih   = (const float*)d_in[3];
    const float* whh   = (const float*)d_in[4];
    const float* bhh   = (const float*)d_in[5];
    const float* lw    = (const float*)d_in[6];
    const float* lb    = (const float*)d_in[7];
    const float* h0    = (const float*)d_in[8];
    float* out = (float*)d_out;

    float *tbl = nullptr, *hs = nullptr;
    cudaGetSymbolAddress((void**)&tbl, g_table);
    cudaGetSymbolAddress((void**)&hs, g_hs);

    const int rec_smem = SM_FLOATS * sizeof(float);   // ~166 KB
    static bool attr_done = false;
    if (!attr_done) {
        cudaFuncSetAttribute(recurrent, cudaFuncAttributeMaxDynamicSharedMemorySize, rec_smem);
        attr_done = true;
    }

    // 1) vocab table: table[v][0:3072] = embed[v]·W_ih^T + b_ih
    gemm_nt<<<dim3(G3 / 128, VV / 64), 256>>>(embed, wih, bih, tbl, G3, 0);
    // 2) persistent recurrence over 513 steps
    recurrent<<<NCTA, 256, rec_smem>>>(whh, bhh, y, h0);
    // 3) out[b][t][:] = hs[t*64+b]·linear_w^T + linear_b  (row remap in epilogue)
    gemm_nt<<<dim3(JJ / 128, (TS * BB) / 64), 256>>>(hs, lw, lb, out, JJ, 1);
}

// round 13
// speedup vs baseline: 1.1062x; 1.1062x over previous
#include <cuda_runtime.h>
#include <cstdint>

#define DD 1024
#define VV 1024
#define BB 64
#define UU 512
#define TS 513           // U+1 steps
#define G3 3072
#define JJ 1024
#define NCTA 128         // 128 CTAs x 8 j-cols each = 1024 gate-triples
#define THREADS 512      // 16 warps -> 4 per SMSP

// recurrent smem layout (floats)
#define WS_FLOATS (1024 * 24)            // W slice [k][24 rows]
#define HB_STRIDE 66                     // h chunk row stride (conflict-free)
#define HB_FLOATS (128 * HB_STRIDE)      // one h chunk [128 k][66]
#define H_OFF WS_FLOATS
#define R_OFF (H_OFF + 2 * HB_FLOATS)    // partial region: 8*24*33 ull = 12672 floats
#define R_ULL (8 * 24 * 33)
#define Y_OFF (R_OFF + 2 * R_ULL)
#define SM_FLOATS (Y_OFF + 64)           // 54208 floats = 216.8 KB

// ---------------- f32x2 packed-FMA helpers ----------------
__device__ __forceinline__ unsigned long long pack2(float x, float y) {
    unsigned long long r;
    asm("mov.b64 %0, {%1, %2};" : "=l"(r) : "f"(x), "f"(y));
    return r;
}
__device__ __forceinline__ unsigned long long fma2(unsigned long long a,
                                                   unsigned long long b,
                                                   unsigned long long c) {
    unsigned long long d;
    asm("fma.rn.f32x2 %0, %1, %2, %3;" : "=l"(d) : "l"(a), "l"(b), "l"(c));
    return d;
}
__device__ __forceinline__ float2 unpack2(unsigned long long v) {
    float2 f;
    asm("mov.b64 {%0, %1}, %2;" : "=f"(f.x), "=f"(f.y) : "l"(v));
    return f;
}

// ---------------- static device scratch (alloc-free rule) ----------------
__device__ __align__(16) float g_table[(size_t)VV * G3];   // W_ih@embed^T + b_ih
__device__ __align__(16) float g_hs[(size_t)TS * BB * DD]; // all hidden states
__device__ __align__(16) float g_hbuf[2][BB * DD];         // ping-pong hidden state
__device__ __align__(16) unsigned g_cnt8[8 * 32];          // arrival counters, 128B apart
__device__ unsigned g_bar_cnt;
__device__ unsigned g_bar_phase;

// ---------------- software grid barrier (init only) ----------------
__device__ __forceinline__ void gsync(unsigned target) {
    __syncthreads();
    if (threadIdx.x == 0) {
        __threadfence();
        unsigned a = atomicAdd(&g_bar_cnt, 1u);
        if (a == (unsigned)gridDim.x - 1u) {
            *(volatile unsigned*)&g_bar_cnt = 0u;
            __threadfence();
            atomicExch(&g_bar_phase, target);
        } else {
            while (*(volatile unsigned*)&g_bar_phase != target) { }
            __threadfence();
        }
    }
    __syncthreads();
}

// ---------------- fp32 GEMM v4 (double-buffered): C = A.B^T + bias ----------------
// A:[M][1024] K-major, B:[N][1024] K-major. Tile 64x128, 256 thr, f32x2 over n.
// M multiple of 64. remap=1: C-row = (m&63)*TS + (m>>6).
__global__ __launch_bounds__(256, 2) void gemm_nt(
    const float* __restrict__ A, const float* __restrict__ Bm,
    const float* __restrict__ bias, float* __restrict__ C,
    int ldc, int remap)
{
    __shared__ float As[2][16][68];
    __shared__ float Bs[2][16][132];
    const int tid = threadIdx.x;
    const int m0 = blockIdx.y * 64;
    const int n0 = blockIdx.x * 128;
    const int tx = tid & 15;
    const int ty = tid >> 4;
    const int ar = tid >> 2, aq = tid & 3;
    const int br0 = (tid) >> 2, bq0 = tid & 3;
    const int br1 = (tid + 256) >> 2, bq1 = tid & 3;

    unsigned long long acc2[4][4];
#pragma unroll
    for (int i = 0; i < 4; i++)
#pragma unroll
        for (int j = 0; j < 4; j++) acc2[i][j] = 0ull;

    {
        float4 av = *(const float4*)(A + (size_t)(m0 + ar) * 1024 + aq * 4);
        As[0][aq * 4 + 0][ar] = av.x; As[0][aq * 4 + 1][ar] = av.y;
        As[0][aq * 4 + 2][ar] = av.z; As[0][aq * 4 + 3][ar] = av.w;
        float4 b0 = *(const float4*)(Bm + (size_t)(n0 + br0) * 1024 + bq0 * 4);
        Bs[0][bq0 * 4 + 0][br0] = b0.x; Bs[0][bq0 * 4 + 1][br0] = b0.y;
        Bs[0][bq0 * 4 + 2][br0] = b0.z; Bs[0][bq0 * 4 + 3][br0] = b0.w;
        float4 b1 = *(const float4*)(Bm + (size_t)(n0 + br1) * 1024 + bq1 * 4);
        Bs[0][bq1 * 4 + 0][br1] = b1.x; Bs[0][bq1 * 4 + 1][br1] = b1.y;
        Bs[0][bq1 * 4 + 2][br1] = b1.z; Bs[0][bq1 * 4 + 3][br1] = b1.w;
    }
    __syncthreads();

#pragma unroll 1
    for (int it = 0; it < 64; it++) {
        const int cur = it & 1;
        float4 avN, b0N, b1N;
        if (it < 63) {
            const int k0 = (it + 1) * 16;
            avN = *(const float4*)(A + (size_t)(m0 + ar) * 1024 + k0 + aq * 4);
            b0N = *(const float4*)(Bm + (size_t)(n0 + br0) * 1024 + k0 + bq0 * 4);
            b1N = *(const float4*)(Bm + (size_t)(n0 + br1) * 1024 + k0 + bq1 * 4);
        }
#pragma unroll
        for (int kk = 0; kk < 16; kk++) {
            unsigned long long rn2[4];
#pragma unroll
            for (int j = 0; j < 4; j++)
                rn2[j] = *(const unsigned long long*)&Bs[cur][kk][tx * 2 + 32 * j];
#pragma unroll
            for (int i = 0; i < 4; i++) {
                float a = As[cur][kk][ty + 16 * i];
                unsigned long long am = pack2(a, a);
#pragma unroll
                for (int j = 0; j < 4; j++)
                    acc2[i][j] = fma2(am, rn2[j], acc2[i][j]);
            }
        }
        if (it < 63) {
            const int nxt = cur ^ 1;
            As[nxt][aq * 4 + 0][ar] = avN.x; As[nxt][aq * 4 + 1][ar] = avN.y;
            As[nxt][aq * 4 + 2][ar] = avN.z; As[nxt][aq * 4 + 3][ar] = avN.w;
            Bs[nxt][bq0 * 4 + 0][br0] = b0N.x; Bs[nxt][bq0 * 4 + 1][br0] = b0N.y;
            Bs[nxt][bq0 * 4 + 2][br0] = b0N.z; Bs[nxt][bq0 * 4 + 3][br0] = b0N.w;
            Bs[nxt][bq1 * 4 + 0][br1] = b1N.x; Bs[nxt][bq1 * 4 + 1][br1] = b1N.y;
            Bs[nxt][bq1 * 4 + 2][br1] = b1N.z; Bs[nxt][bq1 * 4 + 3][br1] = b1N.w;
            __syncthreads();
        }
    }

    float2 b2[4];
#pragma unroll
    for (int j = 0; j < 4; j++)
        b2[j] = *(const float2*)(bias + n0 + tx * 2 + 32 * j);

#pragma unroll
    for (int i = 0; i < 4; i++) {
        int m = m0 + ty + 16 * i;
        int orow = remap ? ((m & 63) * TS + (m >> 6)) : m;
#pragma unroll
        for (int j = 0; j < 4; j++) {
            float2 v = unpack2(acc2[i][j]);
            float2 o = {v.x + b2[j].x, v.y + b2[j].y};
            *(float2*)(C + (size_t)orow * ldc + n0 + tx * 2 + 32 * j) = o;
        }
    }
}

// ---------------- persistent GRU recurrence v5 ----------------
// 128 CTAs x 512 thr (16 warps). CTA owns 24 full-K W_hh rows in smem.
// K split over 16 warps (64 k each); two-stage smem reduction; gates local.
// Step barrier: 8 line-padded arrival counters + thread-0-only sum-poll.
__global__ __launch_bounds__(THREADS, 1) void recurrent(
    const float* __restrict__ Whh, const float* __restrict__ bhh,
    const int* __restrict__ y, const float* __restrict__ h0)
{
    extern __shared__ float smem[];
    float* w_s = smem;                       // [1024 k][24 rows]
    int* y_si = (int*)(smem + Y_OFF);

    const int tid = threadIdx.x;
    const int lane = tid & 31;
    const int warp = tid >> 5;               // 0..15
    const int cta = blockIdx.x;
    const int rg = lane >> 3;                // 0..3 -> rows rg*6..+5
    const int bg = lane & 7;                 // 0..7 -> bpairs bg+8jj
    const int hb_b = tid >> 3;               // 0..63 (h loader)
    const int hb_fq = tid & 7;               // 0..7
    // gate-thread constants (valid for tid < 256)
    const int jl = tid & 7;
    const int bb = (tid >> 3) & 31;
    const int j = cta * 8 + jl;
    const int b0 = 2 * bb, b1 = 2 * bb + 1;

    unsigned target = *(volatile unsigned*)&g_bar_phase;

    // ---- load W slice once: local row rho -> global row (rho/8)*1024 + cta*8 + rho%8
#pragma unroll 4
    for (int p = 0; p < 12; p++) {
        int e = p * THREADS + tid;
        int rho = e >> 8;
        int f4 = e & 255;
        int grow = (rho >> 3) * 1024 + cta * 8 + (rho & 7);
        float4 wv = *(const float4*)(Whh + (size_t)grow * DD + f4 * 4);
        w_s[(f4 * 4 + 0) * 24 + rho] = wv.x;
        w_s[(f4 * 4 + 1) * 24 + rho] = wv.y;
        w_s[(f4 * 4 + 2) * 24 + rho] = wv.z;
        w_s[(f4 * 4 + 3) * 24 + rho] = wv.w;
    }

    // reset counters + broadcast initial_state, then ONE init barrier
    if (cta == 0 && tid < 8) g_cnt8[tid * 32] = 0u;
    for (int e = cta * THREADS + tid; e < BB * DD; e += NCTA * THREADS)
        g_hbuf[0][e] = h0[e & (DD - 1)];
    gsync(++target);

    // loop-invariant gate biases
    const float brr = bhh[j], bzz = bhh[DD + j], bnn = bhh[2 * DD + j];

#pragma unroll 1
    for (int t = 0; t < TS; t++) {
        const float* __restrict__ hc = g_hbuf[t & 1];
        float* __restrict__ hn = g_hbuf[(t + 1) & 1];

        // tokens (overlaps with wait)
        if (tid < BB) y_si[tid] = (t == 0) ? 0 : y[tid * UU + t - 1];

        // thread-0-only wait: all 128 CTAs published step t-1
        if (tid == 0 && t > 0) {
            const unsigned lim = 128u * (unsigned)t;
            unsigned s;
            do {
                s = 0;
#pragma unroll
                for (int q = 0; q < 8; q++) s += *(volatile unsigned*)&g_cnt8[q * 32];
            } while (s < lim);
            __threadfence();
        }
        __syncthreads();

        // stage chunk 0 of h (transposed [k][b], stride 66)
        {
            const float* src = hc + hb_b * DD;
            float* hb = smem + H_OFF;
#pragma unroll
            for (int u = 0; u < 4; u++) {
                float4 p0 = __ldcg((const float4*)(src + (hb_fq + 8 * u) * 4));
                int kap = (hb_fq + 8 * u) * 4;
                hb[(kap + 0) * HB_STRIDE + hb_b] = p0.x;
                hb[(kap + 1) * HB_STRIDE + hb_b] = p0.y;
                hb[(kap + 2) * HB_STRIDE + hb_b] = p0.z;
                hb[(kap + 3) * HB_STRIDE + hb_b] = p0.w;
            }
        }
        __syncthreads();

        // early prefetch of gate operands (tid<256; consumed after mainloop)
        float p_t0r = 0.f, p_t0z = 0.f, p_t0n = 0.f;
        float p_t1r = 0.f, p_t1z = 0.f, p_t1n = 0.f;
        float p_h00 = 0.f, p_h01 = 0.f;
        if (tid < 256) {
            const int tok0 = y_si[b0], tok1 = y_si[b1];
            const float* t0p = g_table + (size_t)tok0 * G3;
            const float* t1p = g_table + (size_t)tok1 * G3;
            p_t0r = __ldcg(t0p + j); p_t0z = __ldcg(t0p + DD + j); p_t0n = __ldcg(t0p + 2 * DD + j);
            p_t1r = __ldcg(t1p + j); p_t1z = __ldcg(t1p + DD + j); p_t1n = __ldcg(t1p + 2 * DD + j);
            p_h00 = __ldcg(hc + (size_t)b0 * DD + j);
            p_h01 = __ldcg(hc + (size_t)b1 * DD + j);
        }

        // ---- mainloop: warp w covers kk = w*8 + kap within each 128-chunk ----
        unsigned long long acc2[6][4];
#pragma unroll
        for (int i = 0; i < 6; i++)
#pragma unroll
            for (int jj = 0; jj < 4; jj++) acc2[i][jj] = 0ull;

#pragma unroll 1
        for (int c = 0; c < 8; c++) {
            float4 pf[4];
            if (c < 7) {
                const float* srcn = hc + hb_b * DD + (c + 1) * 128;
#pragma unroll
                for (int u = 0; u < 4; u++)
                    pf[u] = __ldcg((const float4*)(srcn + (hb_fq + 8 * u) * 4));
            }
            const float* hb = smem + H_OFF + (c & 1) * HB_FLOATS;
            const float* wb = w_s + c * 128 * 24;
#pragma unroll
            for (int kap = 0; kap < 8; kap++) {
                const int kk = warp * 8 + kap;
                unsigned long long rh2[4];
#pragma unroll
                for (int jj = 0; jj < 4; jj++)
                    rh2[jj] = *(const unsigned long long*)&hb[kk * HB_STRIDE + 2 * (bg + 8 * jj)];
#pragma unroll
                for (int i = 0; i < 6; i++) {
                    float wv = wb[kk * 24 + rg * 6 + i];
                    unsigned long long w2 = pack2(wv, wv);
#pragma unroll
                    for (int jj = 0; jj < 4; jj++)
                        acc2[i][jj] = fma2(rh2[jj], w2, acc2[i][jj]);
                }
            }
            if (c < 7) {
                float* hb2 = smem + H_OFF + ((c + 1) & 1) * HB_FLOATS;
#pragma unroll
                for (int u = 0; u < 4; u++) {
                    int kap = (hb_fq + 8 * u) * 4;
                    hb2[(kap + 0) * HB_STRIDE + hb_b] = pf[u].x;
                    hb2[(kap + 1) * HB_STRIDE + hb_b] = pf[u].y;
                    hb2[(kap + 2) * HB_STRIDE + hb_b] = pf[u].z;
                    hb2[(kap + 3) * HB_STRIDE + hb_b] = pf[u].w;
                }
                __syncthreads();
            }
        }

        // ---- two-stage 16->8->1 reduction (dedicated region, no overlay) ----
        unsigned long long* redq = (unsigned long long*)(smem + R_OFF);
        if (warp >= 8) {
#pragma unroll
            for (int i = 0; i < 6; i++)
#pragma unroll
                for (int jj = 0; jj < 4; jj++)
                    redq[((size_t)(warp - 8) * 24 + rg * 6 + i) * 33 + bg + 8 * jj] = acc2[i][jj];
        }
        __syncthreads();
        if (warp < 8) {
            float2* redf = (float2*)redq;
#pragma unroll
            for (int i = 0; i < 6; i++)
#pragma unroll
                for (int jj = 0; jj < 4; jj++) {
                    const size_t idx = ((size_t)warp * 24 + rg * 6 + i) * 33 + bg + 8 * jj;
                    float2 a = unpack2(acc2[i][jj]);
                    float2 b = redf[idx];
                    redf[idx] = make_float2(a.x + b.x, a.y + b.y);
                }
        }
        __syncthreads();

        // ---- reduce 8 slots + gates (tid < 256: jl, bpair bb) ----
        if (tid < 256) {
            const float2* red2 = (const float2*)redq;
            float2 sr = {0.f, 0.f}, sz = {0.f, 0.f}, sn = {0.f, 0.f};
#pragma unroll
            for (int w = 0; w < 8; w++) {
                float2 a = red2[(w * 24 + jl) * 33 + bb];
                float2 b = red2[(w * 24 + 8 + jl) * 33 + bb];
                float2 cpl = red2[(w * 24 + 16 + jl) * 33 + bb];
                sr.x += a.x; sr.y += a.y;
                sz.x += b.x; sz.y += b.y;
                sn.x += cpl.x; sn.y += cpl.y;
            }
            float xr0 = p_t0r + sr.x + brr,      xr1 = p_t1r + sr.y + brr;
            float xz0 = p_t0z + sz.x + bzz,      xz1 = p_t1z + sz.y + bzz;
            float gn0 = sn.x + bnn,              gn1 = sn.y + bnn;
            float r0 = 1.f / (1.f + __expf(-xr0)), r1 = 1.f / (1.f + __expf(-xr1));
            float z0 = 1.f / (1.f + __expf(-xz0)), z1 = 1.f / (1.f + __expf(-xz1));
            float n0 = tanhf(p_t0n + r0 * gn0),    n1 = tanhf(p_t1n + r1 * gn1);
            float hv0 = (1.f - z0) * n0 + z0 * p_h00;
            float hv1 = (1.f - z1) * n1 + z1 * p_h01;
            hn[(size_t)b0 * DD + j] = hv0;
            hn[(size_t)b1 * DD + j] = hv1;
            g_hs[((size_t)t * BB + b0) * DD + j] = hv0;
            g_hs[((size_t)t * BB + b1) * DD + j] = hv1;
        }
        // publish step t (release arrival counter; 16 CTAs per counter word)
        __syncthreads();
        if (tid == 0) {
            __threadfence();
            atomicAdd(&g_cnt8[(cta & 7) * 32], 1u);
        }
    }
}

// ---------------- launch ----------------
extern "C" void kernel_launch(void* const* d_in, const int* in_sizes, int n_in,
                              void* d_out, int out_size) {
    const int*   y     = (const int*)d_in[0];
    const float* embed = (const float*)d_in[1];
    const float* wih   = (const float*)d_in[2];
    const float* bih   = (const float*)d_in[3];
    const float* whh   = (const float*)d_in[4];
    const float* bhh   = (const float*)d_in[5];
    const float* lw    = (const float*)d_in[6];
    const float* lb    = (const float*)d_in[7];
    const float* h0    = (const float*)d_in[8];
    float* out = (float*)d_out;

    float *tbl = nullptr, *hs = nullptr;
    cudaGetSymbolAddress((void**)&tbl, g_table);
    cudaGetSymbolAddress((void**)&hs, g_hs);

    const int rec_smem = SM_FLOATS * sizeof(float);   // ~216.8 KB
    static bool attr_done = false;
    if (!attr_done) {
        cudaFuncSetAttribute(recurrent, cudaFuncAttributeMaxDynamicSharedMemorySize, rec_smem);
        attr_done = true;
    }

    // 1) vocab table: table[v][0:3072] = embed[v]·W_ih^T + b_ih
    gemm_nt<<<dim3(G3 / 128, VV / 64), 256>>>(embed, wih, bih, tbl, G3, 0);
    // 2) persistent recurrence over 513 steps
    recurrent<<<NCTA, THREADS, rec_smem>>>(whh, bhh, y, h0);
    // 3) out[b][t][:] = hs[t*64+b]·linear_w^T + linear_b  (row remap in epilogue)
    gemm_nt<<<dim3(JJ / 128, (TS * BB) / 64), 256>>>(hs, lw, lb, out, JJ, 1);
}

// round 15
// speedup vs baseline: 1.2387x; 1.1197x over previous
#include <cuda_runtime.h>
#include <cuda_bf16.h>
#include <cstdint>

#define DD 1024
#define VV 1024
#define BB 64
#define UU 512
#define TS 513           // U+1 steps
#define G3 3072
#define JJ 1024
#define NCTA 128         // 128 CTAs x 8 j-cols each = 1024 gate-triples
#define THREADS 512      // 16 warps -> 4 per SMSP
#define MTOT (TS * BB)   // 32832 hs rows

// recurrent smem layout (floats)
#define WS_FLOATS (1024 * 24)            // W slice [k][24 rows]
#define HB_STRIDE 66                     // h chunk row stride (conflict-free)
#define HB_FLOATS (128 * HB_STRIDE)      // one h chunk [128 k][66]
#define H_OFF WS_FLOATS
#define R_OFF (H_OFF + 2 * HB_FLOATS)    // partial region: 8*24*33 ull
#define R_ULL (8 * 24 * 33)
#define Y_OFF (R_OFF + 2 * R_ULL)
#define SM_FLOATS (Y_OFF + 64)           // ~216.8 KB

// out_mma smem (bf16 units): 4 tiles x [128 rows][stride 24], double buffered
#define OS_STRIDE 24
#define OS_TILE (128 * OS_STRIDE)        // 3072 bf16 = 6144 B
#define OS_STAGE (4 * OS_TILE)           // 12288 bf16 = 24576 B
#define OS_SMEM_BYTES (2 * OS_STAGE * 2) // 49152 B

// ---------------- f32x2 packed-FMA helpers ----------------
__device__ __forceinline__ unsigned long long pack2(float x, float y) {
    unsigned long long r;
    asm("mov.b64 %0, {%1, %2};" : "=l"(r) : "f"(x), "f"(y));
    return r;
}
__device__ __forceinline__ unsigned long long fma2(unsigned long long a,
                                                   unsigned long long b,
                                                   unsigned long long c) {
    unsigned long long d;
    asm("fma.rn.f32x2 %0, %1, %2, %3;" : "=l"(d) : "l"(a), "l"(b), "l"(c));
    return d;
}
__device__ __forceinline__ float2 unpack2(unsigned long long v) {
    float2 f;
    asm("mov.b64 {%0, %1}, %2;" : "=f"(f.x), "=f"(f.y) : "l"(v));
    return f;
}

// ---------------- mma.sync helper (baseline PTX, valid at compute_103) ----------------
__device__ __forceinline__ void mma16816(float* c, const uint32_t* a, const uint32_t* b) {
    asm volatile(
        "mma.sync.aligned.m16n8k16.row.col.f32.bf16.bf16.f32 "
        "{%0,%1,%2,%3}, {%4,%5,%6,%7}, {%8,%9}, {%0,%1,%2,%3};"
        : "+f"(c[0]), "+f"(c[1]), "+f"(c[2]), "+f"(c[3])
        : "r"(a[0]), "r"(a[1]), "r"(a[2]), "r"(a[3]), "r"(b[0]), "r"(b[1]));
}

// ---------------- static device scratch (alloc-free rule) ----------------
__device__ __align__(16) float g_table[(size_t)VV * G3];     // W_ih@embed^T + b_ih
__device__ __align__(16) __nv_bfloat16 g_hs_hi[(size_t)MTOT * DD];
__device__ __align__(16) __nv_bfloat16 g_hs_lo[(size_t)MTOT * DD];
__device__ __align__(16) __nv_bfloat16 g_lw_hi[(size_t)JJ * DD];
__device__ __align__(16) __nv_bfloat16 g_lw_lo[(size_t)JJ * DD];
__device__ __align__(16) float g_hbuf[2][BB * DD];           // ping-pong hidden state
__device__ __align__(16) unsigned g_cnt8[8 * 32];            // arrival counters, 128B apart
__device__ unsigned g_bar_cnt;
__device__ unsigned g_bar_phase;

// ---------------- software grid barrier (init only) ----------------
__device__ __forceinline__ void gsync(unsigned target) {
    __syncthreads();
    if (threadIdx.x == 0) {
        __threadfence();
        unsigned a = atomicAdd(&g_bar_cnt, 1u);
        if (a == (unsigned)gridDim.x - 1u) {
            *(volatile unsigned*)&g_bar_cnt = 0u;
            __threadfence();
            atomicExch(&g_bar_phase, target);
        } else {
            while (*(volatile unsigned*)&g_bar_phase != target) { }
            __threadfence();
        }
    }
    __syncthreads();
}

// ---------------- fp32 GEMM (double-buffered, f32x2): vocab table ----------------
__global__ __launch_bounds__(256, 2) void gemm_nt(
    const float* __restrict__ A, const float* __restrict__ Bm,
    const float* __restrict__ bias, float* __restrict__ C, int ldc)
{
    __shared__ float As[2][16][68];
    __shared__ float Bs[2][16][132];
    const int tid = threadIdx.x;
    const int m0 = blockIdx.y * 64;
    const int n0 = blockIdx.x * 128;
    const int tx = tid & 15;
    const int ty = tid >> 4;
    const int ar = tid >> 2, aq = tid & 3;
    const int br0 = (tid) >> 2, bq0 = tid & 3;
    const int br1 = (tid + 256) >> 2, bq1 = tid & 3;

    unsigned long long acc2[4][4];
#pragma unroll
    for (int i = 0; i < 4; i++)
#pragma unroll
        for (int j = 0; j < 4; j++) acc2[i][j] = 0ull;

    {
        float4 av = *(const float4*)(A + (size_t)(m0 + ar) * 1024 + aq * 4);
        As[0][aq * 4 + 0][ar] = av.x; As[0][aq * 4 + 1][ar] = av.y;
        As[0][aq * 4 + 2][ar] = av.z; As[0][aq * 4 + 3][ar] = av.w;
        float4 b0 = *(const float4*)(Bm + (size_t)(n0 + br0) * 1024 + bq0 * 4);
        Bs[0][bq0 * 4 + 0][br0] = b0.x; Bs[0][bq0 * 4 + 1][br0] = b0.y;
        Bs[0][bq0 * 4 + 2][br0] = b0.z; Bs[0][bq0 * 4 + 3][br0] = b0.w;
        float4 b1 = *(const float4*)(Bm + (size_t)(n0 + br1) * 1024 + bq1 * 4);
        Bs[0][bq1 * 4 + 0][br1] = b1.x; Bs[0][bq1 * 4 + 1][br1] = b1.y;
        Bs[0][bq1 * 4 + 2][br1] = b1.z; Bs[0][bq1 * 4 + 3][br1] = b1.w;
    }
    __syncthreads();

#pragma unroll 1
    for (int it = 0; it < 64; it++) {
        const int cur = it & 1;
        float4 avN, b0N, b1N;
        if (it < 63) {
            const int k0 = (it + 1) * 16;
            avN = *(const float4*)(A + (size_t)(m0 + ar) * 1024 + k0 + aq * 4);
            b0N = *(const float4*)(Bm + (size_t)(n0 + br0) * 1024 + k0 + bq0 * 4);
            b1N = *(const float4*)(Bm + (size_t)(n0 + br1) * 1024 + k0 + bq1 * 4);
        }
#pragma unroll
        for (int kk = 0; kk < 16; kk++) {
            unsigned long long rn2[4];
#pragma unroll
            for (int j = 0; j < 4; j++)
                rn2[j] = *(const unsigned long long*)&Bs[cur][kk][tx * 2 + 32 * j];
#pragma unroll
            for (int i = 0; i < 4; i++) {
                float a = As[cur][kk][ty + 16 * i];
                unsigned long long am = pack2(a, a);
#pragma unroll
                for (int j = 0; j < 4; j++)
                    acc2[i][j] = fma2(am, rn2[j], acc2[i][j]);
            }
        }
        if (it < 63) {
            const int nxt = cur ^ 1;
            As[nxt][aq * 4 + 0][ar] = avN.x; As[nxt][aq * 4 + 1][ar] = avN.y;
            As[nxt][aq * 4 + 2][ar] = avN.z; As[nxt][aq * 4 + 3][ar] = avN.w;
            Bs[nxt][bq0 * 4 + 0][br0] = b0N.x; Bs[nxt][bq0 * 4 + 1][br0] = b0N.y;
            Bs[nxt][bq0 * 4 + 2][br0] = b0N.z; Bs[nxt][bq0 * 4 + 3][br0] = b0N.w;
            Bs[nxt][bq1 * 4 + 0][br1] = b1N.x; Bs[nxt][bq1 * 4 + 1][br1] = b1N.y;
            Bs[nxt][bq1 * 4 + 2][br1] = b1N.z; Bs[nxt][bq1 * 4 + 3][br1] = b1N.w;
            __syncthreads();
        }
    }

    float2 b2[4];
#pragma unroll
    for (int j = 0; j < 4; j++)
        b2[j] = *(const float2*)(bias + n0 + tx * 2 + 32 * j);

#pragma unroll
    for (int i = 0; i < 4; i++) {
        int m = m0 + ty + 16 * i;
#pragma unroll
        for (int j = 0; j < 4; j++) {
            float2 v = unpack2(acc2[i][j]);
            float2 o = {v.x + b2[j].x, v.y + b2[j].y};
            *(float2*)(C + (size_t)m * ldc + n0 + tx * 2 + 32 * j) = o;
        }
    }
}

// ---------------- lw -> bf16 (hi, lo) split ----------------
__global__ void convert_lw(const float* __restrict__ w) {
    int i = blockIdx.x * 256 + threadIdx.x;
    if (i < JJ * DD) {
        float v = w[i];
        __nv_bfloat16 h = __float2bfloat16(v);
        g_lw_hi[i] = h;
        g_lw_lo[i] = __float2bfloat16(v - __bfloat162float(h));
    }
}

// ---------------- persistent GRU recurrence (R13) + bf16 hs stores ----------------
__global__ __launch_bounds__(THREADS, 1) void recurrent(
    const float* __restrict__ Whh, const float* __restrict__ bhh,
    const int* __restrict__ y, const float* __restrict__ h0)
{
    extern __shared__ float smem[];
    float* w_s = smem;                       // [1024 k][24 rows]
    int* y_si = (int*)(smem + Y_OFF);

    const int tid = threadIdx.x;
    const int lane = tid & 31;
    const int warp = tid >> 5;               // 0..15
    const int cta = blockIdx.x;
    const int rg = lane >> 3;                // 0..3 -> rows rg*6..+5
    const int bg = lane & 7;                 // 0..7 -> bpairs bg+8jj
    const int hb_b = tid >> 3;               // 0..63 (h loader)
    const int hb_fq = tid & 7;               // 0..7
    const int jl = tid & 7;
    const int bb = (tid >> 3) & 31;
    const int j = cta * 8 + jl;
    const int b0 = 2 * bb, b1 = 2 * bb + 1;

    unsigned target = *(volatile unsigned*)&g_bar_phase;

#pragma unroll 4
    for (int p = 0; p < 12; p++) {
        int e = p * THREADS + tid;
        int rho = e >> 8;
        int f4 = e & 255;
        int grow = (rho >> 3) * 1024 + cta * 8 + (rho & 7);
        float4 wv = *(const float4*)(Whh + (size_t)grow * DD + f4 * 4);
        w_s[(f4 * 4 + 0) * 24 + rho] = wv.x;
        w_s[(f4 * 4 + 1) * 24 + rho] = wv.y;
        w_s[(f4 * 4 + 2) * 24 + rho] = wv.z;
        w_s[(f4 * 4 + 3) * 24 + rho] = wv.w;
    }

    if (cta == 0 && tid < 8) g_cnt8[tid * 32] = 0u;
    for (int e = cta * THREADS + tid; e < BB * DD; e += NCTA * THREADS)
        g_hbuf[0][e] = h0[e & (DD - 1)];
    gsync(++target);

    const float brr = bhh[j], bzz = bhh[DD + j], bnn = bhh[2 * DD + j];

#pragma unroll 1
    for (int t = 0; t < TS; t++) {
        const float* __restrict__ hc = g_hbuf[t & 1];
        float* __restrict__ hn = g_hbuf[(t + 1) & 1];

        if (tid < BB) y_si[tid] = (t == 0) ? 0 : y[tid * UU + t - 1];

        if (tid == 0 && t > 0) {
            const unsigned lim = 128u * (unsigned)t;
            unsigned s;
            do {
                s = 0;
#pragma unroll
                for (int q = 0; q < 8; q++) s += *(volatile unsigned*)&g_cnt8[q * 32];
            } while (s < lim);
            __threadfence();
        }
        __syncthreads();

        {
            const float* src = hc + hb_b * DD;
            float* hb = smem + H_OFF;
#pragma unroll
            for (int u = 0; u < 4; u++) {
                float4 p0 = __ldcg((const float4*)(src + (hb_fq + 8 * u) * 4));
                int kap = (hb_fq + 8 * u) * 4;
                hb[(kap + 0) * HB_STRIDE + hb_b] = p0.x;
                hb[(kap + 1) * HB_STRIDE + hb_b] = p0.y;
                hb[(kap + 2) * HB_STRIDE + hb_b] = p0.z;
                hb[(kap + 3) * HB_STRIDE + hb_b] = p0.w;
            }
        }
        __syncthreads();

        float p_t0r = 0.f, p_t0z = 0.f, p_t0n = 0.f;
        float p_t1r = 0.f, p_t1z = 0.f, p_t1n = 0.f;
        float p_h00 = 0.f, p_h01 = 0.f;
        if (tid < 256) {
            const int tok0 = y_si[b0], tok1 = y_si[b1];
            const float* t0p = g_table + (size_t)tok0 * G3;
            const float* t1p = g_table + (size_t)tok1 * G3;
            p_t0r = __ldcg(t0p + j); p_t0z = __ldcg(t0p + DD + j); p_t0n = __ldcg(t0p + 2 * DD + j);
            p_t1r = __ldcg(t1p + j); p_t1z = __ldcg(t1p + DD + j); p_t1n = __ldcg(t1p + 2 * DD + j);
            p_h00 = __ldcg(hc + (size_t)b0 * DD + j);
            p_h01 = __ldcg(hc + (size_t)b1 * DD + j);
        }

        unsigned long long acc2[6][4];
#pragma unroll
        for (int i = 0; i < 6; i++)
#pragma unroll
            for (int jj = 0; jj < 4; jj++) acc2[i][jj] = 0ull;

#pragma unroll 1
        for (int c = 0; c < 8; c++) {
            float4 pf[4];
            if (c < 7) {
                const float* srcn = hc + hb_b * DD + (c + 1) * 128;
#pragma unroll
                for (int u = 0; u < 4; u++)
                    pf[u] = __ldcg((const float4*)(srcn + (hb_fq + 8 * u) * 4));
            }
            const float* hb = smem + H_OFF + (c & 1) * HB_FLOATS;
            const float* wb = w_s + c * 128 * 24;
#pragma unroll
            for (int kap = 0; kap < 8; kap++) {
                const int kk = warp * 8 + kap;
                unsigned long long rh2[4];
#pragma unroll
                for (int jj = 0; jj < 4; jj++)
                    rh2[jj] = *(const unsigned long long*)&hb[kk * HB_STRIDE + 2 * (bg + 8 * jj)];
#pragma unroll
                for (int i = 0; i < 6; i++) {
                    float wv = wb[kk * 24 + rg * 6 + i];
                    unsigned long long w2 = pack2(wv, wv);
#pragma unroll
                    for (int jj = 0; jj < 4; jj++)
                        acc2[i][jj] = fma2(rh2[jj], w2, acc2[i][jj]);
                }
            }
            if (c < 7) {
                float* hb2 = smem + H_OFF + ((c + 1) & 1) * HB_FLOATS;
#pragma unroll
                for (int u = 0; u < 4; u++) {
                    int kap = (hb_fq + 8 * u) * 4;
                    hb2[(kap + 0) * HB_STRIDE + hb_b] = pf[u].x;
                    hb2[(kap + 1) * HB_STRIDE + hb_b] = pf[u].y;
                    hb2[(kap + 2) * HB_STRIDE + hb_b] = pf[u].z;
                    hb2[(kap + 3) * HB_STRIDE + hb_b] = pf[u].w;
                }
                __syncthreads();
            }
        }

        unsigned long long* redq = (unsigned long long*)(smem + R_OFF);
        if (warp >= 8) {
#pragma unroll
            for (int i = 0; i < 6; i++)
#pragma unroll
                for (int jj = 0; jj < 4; jj++)
                    redq[((size_t)(warp - 8) * 24 + rg * 6 + i) * 33 + bg + 8 * jj] = acc2[i][jj];
        }
        __syncthreads();
        if (warp < 8) {
            float2* redf = (float2*)redq;
#pragma unroll
            for (int i = 0; i < 6; i++)
#pragma unroll
                for (int jj = 0; jj < 4; jj++) {
                    const size_t idx = ((size_t)warp * 24 + rg * 6 + i) * 33 + bg + 8 * jj;
                    float2 a = unpack2(acc2[i][jj]);
                    float2 b = redf[idx];
                    redf[idx] = make_float2(a.x + b.x, a.y + b.y);
                }
        }
        __syncthreads();

        if (tid < 256) {
            const float2* red2 = (const float2*)redq;
            float2 sr = {0.f, 0.f}, sz = {0.f, 0.f}, sn = {0.f, 0.f};
#pragma unroll
            for (int w = 0; w < 8; w++) {
                float2 a = red2[(w * 24 + jl) * 33 + bb];
                float2 b = red2[(w * 24 + 8 + jl) * 33 + bb];
                float2 cpl = red2[(w * 24 + 16 + jl) * 33 + bb];
                sr.x += a.x; sr.y += a.y;
                sz.x += b.x; sz.y += b.y;
                sn.x += cpl.x; sn.y += cpl.y;
            }
            float xr0 = p_t0r + sr.x + brr,      xr1 = p_t1r + sr.y + brr;
            float xz0 = p_t0z + sz.x + bzz,      xz1 = p_t1z + sz.y + bzz;
            float gn0 = sn.x + bnn,              gn1 = sn.y + bnn;
            float r0 = 1.f / (1.f + __expf(-xr0)), r1 = 1.f / (1.f + __expf(-xr1));
            float z0 = 1.f / (1.f + __expf(-xz0)), z1 = 1.f / (1.f + __expf(-xz1));
            float n0 = tanhf(p_t0n + r0 * gn0),    n1 = tanhf(p_t1n + r1 * gn1);
            float hv0 = (1.f - z0) * n0 + z0 * p_h00;
            float hv1 = (1.f - z1) * n1 + z1 * p_h01;
            hn[(size_t)b0 * DD + j] = hv0;
            hn[(size_t)b1 * DD + j] = hv1;
            // split-bf16 hs for the tensor-core out-GEMM
            __nv_bfloat16 h0h = __float2bfloat16(hv0);
            __nv_bfloat16 h1h = __float2bfloat16(hv1);
            const size_t i0 = ((size_t)t * BB + b0) * DD + j;
            const size_t i1 = ((size_t)t * BB + b1) * DD + j;
            g_hs_hi[i0] = h0h;
            g_hs_lo[i0] = __float2bfloat16(hv0 - __bfloat162float(h0h));
            g_hs_hi[i1] = h1h;
            g_hs_lo[i1] = __float2bfloat16(hv1 - __bfloat162float(h1h));
        }
        __syncthreads();
        if (tid == 0) {
            __threadfence();
            atomicAdd(&g_cnt8[(cta & 7) * 32], 1u);
        }
    }
}

// ---------------- mma.sync bf16-split out-GEMM ----------------
// out[b*TS+t][n] = hs[t*64+b].lw[n] + bias[n];  out ~= Ah.Bh + Ah.Bl + Al.Bh
// CTA 128m x 128n, 8 warps (4m x 2n), warp 32m x 64n, K staged 16/iter.
__global__ __launch_bounds__(256, 2) void out_mma(
    const float* __restrict__ bias, float* __restrict__ out)
{
    extern __shared__ __align__(16) __nv_bfloat16 osm[];
    const int tid = threadIdx.x;
    const int wid = tid >> 5;
    const int lane = tid & 31;
    const int wm = wid & 3;          // warp m-group (0..3)
    const int wn = wid >> 2;         // warp n-group (0..1)
    const int g = lane >> 2;         // 0..7
    const int ct = lane & 3;         // 0..3
    const int n0 = blockIdx.x * 128;
    const int m0 = blockIdx.y * 128;

    // loader mapping: 4 uint4 per thread per stage; e = i*256+tid
    // tile = e>>8 (0:Ah 1:Al 2:Bh 3:Bl), r = (e>>1)&127, q = e&1
    const __nv_bfloat16* srcs[4];
    {
        int r0 = (tid >> 1) & 127;
        int arow = m0 + r0; if (arow >= MTOT) arow = MTOT - 1;
        srcs[0] = g_hs_hi + (size_t)arow * DD;
        srcs[1] = g_hs_lo + (size_t)arow * DD;
        srcs[2] = g_lw_hi + (size_t)(n0 + r0) * DD;
        srcs[3] = g_lw_lo + (size_t)(n0 + r0) * DD;
    }

    float acc[2][8][4];
#pragma unroll
    for (int mt = 0; mt < 2; mt++)
#pragma unroll
        for (int nt = 0; nt < 8; nt++)
#pragma unroll
            for (int u = 0; u < 4; u++) acc[mt][nt][u] = 0.f;

    // stage 0 direct load (kc = 0)
#pragma unroll
    for (int i = 0; i < 4; i++) {
        int e = i * 256 + tid;
        int tile = e >> 8;
        int r = (e >> 1) & 127;
        int q = e & 1;
        // same r as loader mapping (r == (tid>>1)&127 for all i): reuse srcs
        uint4 v = *(const uint4*)(srcs[tile] + q * 8);
        *(uint4*)(osm + tile * OS_TILE + r * OS_STRIDE + q * 8) = v;
    }
    __syncthreads();

    const int fm = wm * 32 + g;          // A frag base row (+mt*16, +8)
    const int fn = wn * 64 + g;          // B frag base row (+nt*8)

#pragma unroll 1
    for (int kc = 0; kc < 64; kc++) {
        const int cur = kc & 1;
        uint4 pre[4];
        if (kc < 63) {
            const int ko = (kc + 1) * 16;
#pragma unroll
            for (int i = 0; i < 4; i++) {
                int e = i * 256 + tid;
                int tile = e >> 8;
                int q = e & 1;
                pre[i] = *(const uint4*)(srcs[tile] + ko + q * 8);
            }
        }
        const __nv_bfloat16* st = osm + cur * OS_STAGE;
        // A fragments (hi & lo, 2 m-tiles)
        uint32_t ah[2][4], al[2][4];
#pragma unroll
        for (int mt = 0; mt < 2; mt++) {
            int base = (fm + mt * 16) * OS_STRIDE + ct * 2;
            ah[mt][0] = *(const uint32_t*)(st + base);
            ah[mt][1] = *(const uint32_t*)(st + base + 8 * OS_STRIDE);
            ah[mt][2] = *(const uint32_t*)(st + base + 8);
            ah[mt][3] = *(const uint32_t*)(st + base + 8 * OS_STRIDE + 8);
            const __nv_bfloat16* stl = st + OS_TILE;
            al[mt][0] = *(const uint32_t*)(stl + base);
            al[mt][1] = *(const uint32_t*)(stl + base + 8 * OS_STRIDE);
            al[mt][2] = *(const uint32_t*)(stl + base + 8);
            al[mt][3] = *(const uint32_t*)(stl + base + 8 * OS_STRIDE + 8);
        }
#pragma unroll
        for (int nt = 0; nt < 8; nt++) {
            int base = (fn + nt * 8) * OS_STRIDE + ct * 2;
            uint32_t bh[2], bl[2];
            const __nv_bfloat16* sbh = st + 2 * OS_TILE;
            const __nv_bfloat16* sbl = st + 3 * OS_TILE;
            bh[0] = *(const uint32_t*)(sbh + base);
            bh[1] = *(const uint32_t*)(sbh + base + 8);
            bl[0] = *(const uint32_t*)(sbl + base);
            bl[1] = *(const uint32_t*)(sbl + base + 8);
#pragma unroll
            for (int mt = 0; mt < 2; mt++) {
                mma16816(acc[mt][nt], ah[mt], bh);
                mma16816(acc[mt][nt], ah[mt], bl);
                mma16816(acc[mt][nt], al[mt], bh);
            }
        }
        if (kc < 63) {
            __nv_bfloat16* dn = osm + (cur ^ 1) * OS_STAGE;
#pragma unroll
            for (int i = 0; i < 4; i++) {
                int e = i * 256 + tid;
                int tile = e >> 8;
                int r = (e >> 1) & 127;
                int q = e & 1;
                *(uint4*)(dn + tile * OS_TILE + r * OS_STRIDE + q * 8) = pre[i];
            }
            __syncthreads();
        }
    }

    // epilogue: remap rows (m -> b*TS + t), add bias
#pragma unroll
    for (int mt = 0; mt < 2; mt++) {
        const int mA = m0 + wm * 32 + mt * 16 + g;
        const int mB = mA + 8;
#pragma unroll
        for (int nt = 0; nt < 8; nt++) {
            const int col = n0 + wn * 64 + nt * 8 + ct * 2;
            float2 bv = *(const float2*)(bias + col);
            if (mA < MTOT) {
                float* o = out + ((size_t)(mA & 63) * TS + (mA >> 6)) * JJ + col;
                o[0] = acc[mt][nt][0] + bv.x;
                o[1] = acc[mt][nt][1] + bv.y;
            }
            if (mB < MTOT) {
                float* o = out + ((size_t)(mB & 63) * TS + (mB >> 6)) * JJ + col;
                o[0] = acc[mt][nt][2] + bv.x;
                o[1] = acc[mt][nt][3] + bv.y;
            }
        }
    }
}

// ---------------- launch ----------------
extern "C" void kernel_launch(void* const* d_in, const int* in_sizes, int n_in,
                              void* d_out, int out_size) {
    const int*   y     = (const int*)d_in[0];
    const float* embed = (const float*)d_in[1];
    const float* wih   = (const float*)d_in[2];
    const float* bih   = (const float*)d_in[3];
    const float* whh   = (const float*)d_in[4];
    const float* bhh   = (const float*)d_in[5];
    const float* lw    = (const float*)d_in[6];
    const float* lb    = (const float*)d_in[7];
    const float* h0    = (const float*)d_in[8];
    float* out = (float*)d_out;

    float* tbl = nullptr;
    cudaGetSymbolAddress((void**)&tbl, g_table);

    const int rec_smem = SM_FLOATS * sizeof(float);   // ~216.8 KB
    static bool attr_done = false;
    if (!attr_done) {
        cudaFuncSetAttribute(recurrent, cudaFuncAttributeMaxDynamicSharedMemorySize, rec_smem);
        cudaFuncSetAttribute(out_mma, cudaFuncAttributeMaxDynamicSharedMemorySize, OS_SMEM_BYTES);
        attr_done = true;
    }

    // 1) vocab table: table[v][0:3072] = embed[v]·W_ih^T + b_ih
    gemm_nt<<<dim3(G3 / 128, VV / 64), 256>>>(embed, wih, bih, tbl, G3);
    // 2) linear_w -> bf16 (hi, lo)
    convert_lw<<<(JJ * DD + 255) / 256, 256>>>(lw);
    // 3) persistent recurrence over 513 steps (writes split-bf16 hs)
    recurrent<<<NCTA, THREADS, rec_smem>>>(whh, bhh, y, h0);
    // 4) tensor-core (HMMA) out-GEMM with remap epilogue
    out_mma<<<dim3(JJ / 128, (MTOT + 127) / 128), 256, OS_SMEM_BYTES>>>(lb, out);
}

// round 16
// speedup vs baseline: 1.5911x; 1.2845x over previous
#include <cuda_runtime.h>
#include <cuda_bf16.h>
#include <cstdint>

#define DD 1024
#define VV 1024
#define BB 64
#define UU 512
#define TS 513           // U+1 steps
#define G3 3072
#define JJ 1024
#define NCTA 128         // 128 CTAs x 8 j-cols each
#define THREADS 512      // 16 warps
#define MTOT (TS * BB)   // 32832 hs rows

// ---- recurrent dynamic smem byte offsets ----
#define RW_HI 0                      // W hi bf16 [24][1032]
#define RW_LO 49536                  // W lo bf16 [24][1032]
#define RHS0 99072                   // h stages (2x): [64][136] hi + lo
#define RSTG 34816                   // one stage bytes (hi+lo)
#define RHLO 17408                   // lo offset within stage
#define RGH 168704                   // gh exchange [64][26] f32
#define RY  175360                   // tokens
#define REC_SMEM (RY + 256)

// out_mma smem (bf16 units): 4 tiles x [128 rows][stride 24], double buffered
#define OS_STRIDE 24
#define OS_TILE (128 * OS_STRIDE)
#define OS_STAGE (4 * OS_TILE)
#define OS_SMEM_BYTES (2 * OS_STAGE * 2)

// ---------------- f32x2 packed-FMA helpers ----------------
__device__ __forceinline__ unsigned long long pack2(float x, float y) {
    unsigned long long r;
    asm("mov.b64 %0, {%1, %2};" : "=l"(r) : "f"(x), "f"(y));
    return r;
}
__device__ __forceinline__ unsigned long long fma2(unsigned long long a,
                                                   unsigned long long b,
                                                   unsigned long long c) {
    unsigned long long d;
    asm("fma.rn.f32x2 %0, %1, %2, %3;" : "=l"(d) : "l"(a), "l"(b), "l"(c));
    return d;
}
__device__ __forceinline__ float2 unpack2(unsigned long long v) {
    float2 f;
    asm("mov.b64 {%0, %1}, %2;" : "=f"(f.x), "=f"(f.y) : "l"(v));
    return f;
}

// ---------------- mma.sync / ldmatrix (baseline PTX, OK at compute_103) ----------------
__device__ __forceinline__ void mma16816(float* c, const uint32_t* a, const uint32_t* b) {
    asm volatile(
        "mma.sync.aligned.m16n8k16.row.col.f32.bf16.bf16.f32 "
        "{%0,%1,%2,%3}, {%4,%5,%6,%7}, {%8,%9}, {%0,%1,%2,%3};"
        : "+f"(c[0]), "+f"(c[1]), "+f"(c[2]), "+f"(c[3])
        : "r"(a[0]), "r"(a[1]), "r"(a[2]), "r"(a[3]), "r"(b[0]), "r"(b[1]));
}
__device__ __forceinline__ void ldsm_x4(uint32_t* r, uint32_t saddr) {
    asm volatile("ldmatrix.sync.aligned.m8n8.x4.shared.b16 {%0,%1,%2,%3}, [%4];"
        : "=r"(r[0]), "=r"(r[1]), "=r"(r[2]), "=r"(r[3]) : "r"(saddr));
}
__device__ __forceinline__ void ldsm_x2(uint32_t* r, uint32_t saddr) {
    asm volatile("ldmatrix.sync.aligned.m8n8.x2.shared.b16 {%0,%1}, [%2];"
        : "=r"(r[0]), "=r"(r[1]) : "r"(saddr));
}
__device__ __forceinline__ uint32_t smem_u32(const void* p) {
    uint32_t a;
    asm("{ .reg .u64 t; cvta.to.shared.u64 t, %1; cvt.u32.u64 %0, t; }" : "=r"(a) : "l"(p));
    return a;
}

// ---------------- static device scratch (alloc-free rule) ----------------
__device__ __align__(16) float g_table[(size_t)VV * G3];
__device__ __align__(16) __nv_bfloat16 g_hs_hi[(size_t)MTOT * DD];
__device__ __align__(16) __nv_bfloat16 g_hs_lo[(size_t)MTOT * DD];
__device__ __align__(16) __nv_bfloat16 g_lw_hi[(size_t)JJ * DD];
__device__ __align__(16) __nv_bfloat16 g_lw_lo[(size_t)JJ * DD];
__device__ __align__(16) float g_hbuf[2][BB * DD];            // fp32 h (gates path)
__device__ __align__(16) __nv_bfloat16 g_hb_hi[2][BB * DD];   // split-bf16 h (MMA path)
__device__ __align__(16) __nv_bfloat16 g_hb_lo[2][BB * DD];
__device__ __align__(16) unsigned g_cnt8[8 * 32];
__device__ unsigned g_bar_cnt;
__device__ unsigned g_bar_phase;

// ---------------- software grid barrier (init only) ----------------
__device__ __forceinline__ void gsync(unsigned target) {
    __syncthreads();
    if (threadIdx.x == 0) {
        __threadfence();
        unsigned a = atomicAdd(&g_bar_cnt, 1u);
        if (a == (unsigned)gridDim.x - 1u) {
            *(volatile unsigned*)&g_bar_cnt = 0u;
            __threadfence();
            atomicExch(&g_bar_phase, target);
        } else {
            while (*(volatile unsigned*)&g_bar_phase != target) { }
            __threadfence();
        }
    }
    __syncthreads();
}

// ---------------- fp32 GEMM (double-buffered, f32x2): vocab table ----------------
__global__ __launch_bounds__(256, 2) void gemm_nt(
    const float* __restrict__ A, const float* __restrict__ Bm,
    const float* __restrict__ bias, float* __restrict__ C, int ldc)
{
    __shared__ float As[2][16][68];
    __shared__ float Bs[2][16][132];
    const int tid = threadIdx.x;
    const int m0 = blockIdx.y * 64;
    const int n0 = blockIdx.x * 128;
    const int tx = tid & 15;
    const int ty = tid >> 4;
    const int ar = tid >> 2, aq = tid & 3;
    const int br0 = (tid) >> 2, bq0 = tid & 3;
    const int br1 = (tid + 256) >> 2, bq1 = tid & 3;

    unsigned long long acc2[4][4];
#pragma unroll
    for (int i = 0; i < 4; i++)
#pragma unroll
        for (int j = 0; j < 4; j++) acc2[i][j] = 0ull;

    {
        float4 av = *(const float4*)(A + (size_t)(m0 + ar) * 1024 + aq * 4);
        As[0][aq * 4 + 0][ar] = av.x; As[0][aq * 4 + 1][ar] = av.y;
        As[0][aq * 4 + 2][ar] = av.z; As[0][aq * 4 + 3][ar] = av.w;
        float4 b0 = *(const float4*)(Bm + (size_t)(n0 + br0) * 1024 + bq0 * 4);
        Bs[0][bq0 * 4 + 0][br0] = b0.x; Bs[0][bq0 * 4 + 1][br0] = b0.y;
        Bs[0][bq0 * 4 + 2][br0] = b0.z; Bs[0][bq0 * 4 + 3][br0] = b0.w;
        float4 b1 = *(const float4*)(Bm + (size_t)(n0 + br1) * 1024 + bq1 * 4);
        Bs[0][bq1 * 4 + 0][br1] = b1.x; Bs[0][bq1 * 4 + 1][br1] = b1.y;
        Bs[0][bq1 * 4 + 2][br1] = b1.z; Bs[0][bq1 * 4 + 3][br1] = b1.w;
    }
    __syncthreads();

#pragma unroll 1
    for (int it = 0; it < 64; it++) {
        const int cur = it & 1;
        float4 avN, b0N, b1N;
        if (it < 63) {
            const int k0 = (it + 1) * 16;
            avN = *(const float4*)(A + (size_t)(m0 + ar) * 1024 + k0 + aq * 4);
            b0N = *(const float4*)(Bm + (size_t)(n0 + br0) * 1024 + k0 + bq0 * 4);
            b1N = *(const float4*)(Bm + (size_t)(n0 + br1) * 1024 + k0 + bq1 * 4);
        }
#pragma unroll
        for (int kk = 0; kk < 16; kk++) {
            unsigned long long rn2[4];
#pragma unroll
            for (int j = 0; j < 4; j++)
                rn2[j] = *(const unsigned long long*)&Bs[cur][kk][tx * 2 + 32 * j];
#pragma unroll
            for (int i = 0; i < 4; i++) {
                float a = As[cur][kk][ty + 16 * i];
                unsigned long long am = pack2(a, a);
#pragma unroll
                for (int j = 0; j < 4; j++)
                    acc2[i][j] = fma2(am, rn2[j], acc2[i][j]);
            }
        }
        if (it < 63) {
            const int nxt = cur ^ 1;
            As[nxt][aq * 4 + 0][ar] = avN.x; As[nxt][aq * 4 + 1][ar] = avN.y;
            As[nxt][aq * 4 + 2][ar] = avN.z; As[nxt][aq * 4 + 3][ar] = avN.w;
            Bs[nxt][bq0 * 4 + 0][br0] = b0N.x; Bs[nxt][bq0 * 4 + 1][br0] = b0N.y;
            Bs[nxt][bq0 * 4 + 2][br0] = b0N.z; Bs[nxt][bq0 * 4 + 3][br0] = b0N.w;
            Bs[nxt][bq1 * 4 + 0][br1] = b1N.x; Bs[nxt][bq1 * 4 + 1][br1] = b1N.y;
            Bs[nxt][bq1 * 4 + 2][br1] = b1N.z; Bs[nxt][bq1 * 4 + 3][br1] = b1N.w;
            __syncthreads();
        }
    }

    float2 b2[4];
#pragma unroll
    for (int j = 0; j < 4; j++)
        b2[j] = *(const float2*)(bias + n0 + tx * 2 + 32 * j);

#pragma unroll
    for (int i = 0; i < 4; i++) {
        int m = m0 + ty + 16 * i;
#pragma unroll
        for (int j = 0; j < 4; j++) {
            float2 v = unpack2(acc2[i][j]);
            float2 o = {v.x + b2[j].x, v.y + b2[j].y};
            *(float2*)(C + (size_t)m * ldc + n0 + tx * 2 + 32 * j) = o;
        }
    }
}

// ---------------- lw -> bf16 (hi, lo) split ----------------
__global__ void convert_lw(const float* __restrict__ w) {
    int i = blockIdx.x * 256 + threadIdx.x;
    if (i < JJ * DD) {
        float v = w[i];
        __nv_bfloat16 h = __float2bfloat16(v);
        g_lw_hi[i] = h;
        g_lw_lo[i] = __float2bfloat16(v - __bfloat162float(h));
    }
}

// ---------------- persistent GRU recurrence v6: HMMA step-GEMM ----------------
// 128 CTAs x 512 thr. CTA owns 24 W rows (8 j x 3 gates), split-bf16 in smem.
// 12 compute warps own (mt 0..3, nt 0..2) with FULL K in 3 register chains.
// h staged per 128-k chunk (split bf16), consumed via ldmatrix. No cross-warp
// reduction; gates computed by 512 threads from a 6.7KB smem exchange.
__global__ __launch_bounds__(THREADS, 1) void recurrent(
    const float* __restrict__ Whh, const float* __restrict__ bhh,
    const int* __restrict__ y, const float* __restrict__ h0)
{
    extern __shared__ __align__(16) char rsm[];
    __nv_bfloat16* w_hi = (__nv_bfloat16*)(rsm + RW_HI);
    __nv_bfloat16* w_lo = (__nv_bfloat16*)(rsm + RW_LO);
    float* gh_s = (float*)(rsm + RGH);
    int* y_si = (int*)(rsm + RY);
    const uint32_t sb = smem_u32(rsm);

    const int tid = threadIdx.x;
    const int lane = tid & 31;
    const int warp = tid >> 5;
    const int cta = blockIdx.x;

    // gate-thread constants: thread = (batch gb, local col jl)
    const int gb = tid >> 3;
    const int jl = tid & 7;
    const int j = cta * 8 + jl;

    // mma constants (compute warps 0..11)
    const int mt = warp & 3;
    const int nt = warp >> 2;
    const int lt = lane >> 3, lrr = lane & 7;
    const uint32_t aoff = ((uint32_t)(mt * 16 + (lt & 1) * 8 + lrr) * 136 + (uint32_t)(lt >> 1) * 8) * 2;
    const uint32_t boff = ((uint32_t)(nt * 8 + lrr) * 1032 + (uint32_t)((lane >> 3) & 1) * 8) * 2;

    unsigned target = *(volatile unsigned*)&g_bar_phase;

    // ---- W slice -> split bf16 smem, once ----
#pragma unroll 4
    for (int p = 0; p < 12; p++) {
        int e = p * THREADS + tid;
        int rho = e >> 8;
        int f4 = e & 255;
        int grow = (rho >> 3) * 1024 + cta * 8 + (rho & 7);
        float4 wv = *(const float4*)(Whh + (size_t)grow * DD + f4 * 4);
        int u = rho * 1032 + f4 * 4;
        __nv_bfloat16 a0 = __float2bfloat16(wv.x), a1 = __float2bfloat16(wv.y);
        __nv_bfloat16 a2 = __float2bfloat16(wv.z), a3 = __float2bfloat16(wv.w);
        w_hi[u + 0] = a0; w_hi[u + 1] = a1; w_hi[u + 2] = a2; w_hi[u + 3] = a3;
        w_lo[u + 0] = __float2bfloat16(wv.x - __bfloat162float(a0));
        w_lo[u + 1] = __float2bfloat16(wv.y - __bfloat162float(a1));
        w_lo[u + 2] = __float2bfloat16(wv.z - __bfloat162float(a2));
        w_lo[u + 3] = __float2bfloat16(wv.w - __bfloat162float(a3));
    }

    // counters + initial state
    if (cta == 0 && tid < 8) g_cnt8[tid * 32] = 0u;
    for (int e = cta * THREADS + tid; e < BB * DD; e += NCTA * THREADS) {
        float v = h0[e & (DD - 1)];
        g_hbuf[0][e] = v;
        __nv_bfloat16 hh = __float2bfloat16(v);
        g_hb_hi[0][e] = hh;
        g_hb_lo[0][e] = __float2bfloat16(v - __bfloat162float(hh));
    }
    gsync(++target);

    const float brr = bhh[j], bzz = bhh[DD + j], bnn = bhh[2 * DD + j];

#pragma unroll 1
    for (int t = 0; t < TS; t++) {
        const int pp = t & 1, pn = pp ^ 1;

        if (tid < BB) y_si[tid] = (t == 0) ? 0 : y[tid * UU + t - 1];

        if (tid == 0 && t > 0) {
            const unsigned lim = 128u * (unsigned)t;
            unsigned s;
            do {
                s = 0;
#pragma unroll
                for (int q = 0; q < 8; q++) s += *(volatile unsigned*)&g_cnt8[q * 32];
            } while (s < lim);
            __threadfence();
        }
        __syncthreads();

        // stage chunk 0 (h hi/lo, [b][k] -> [b][136])
        {
            const uint4* gh_ = (const uint4*)g_hb_hi[pp];
            const uint4* gl_ = (const uint4*)g_hb_lo[pp];
#pragma unroll
            for (int s = 0; s < 2; s++) {
                int e = tid + s * 512;
                int r = e >> 4, q = e & 15;
                uint4 vh = __ldcg(gh_ + r * 128 + q);
                uint4 vl = __ldcg(gl_ + r * 128 + q);
                *(uint4*)(rsm + RHS0 + (r * 136 + q * 8) * 2) = vh;
                *(uint4*)(rsm + RHS0 + RHLO + (r * 136 + q * 8) * 2) = vl;
            }
        }
        __syncthreads();

        // gate operand prefetch (hidden under mainloop)
        const int tok = y_si[gb];
        const float* tp = g_table + (size_t)tok * G3;
        const float ptr_ = __ldcg(tp + j);
        const float ptz = __ldcg(tp + DD + j);
        const float ptn = __ldcg(tp + 2 * DD + j);
        const float phv = __ldcg(g_hbuf[pp] + gb * DD + j);

        // ---- mainloop: 8 chunks of 128 k ----
        float c0[4] = {0,0,0,0}, c1[4] = {0,0,0,0}, c2[4] = {0,0,0,0};
#pragma unroll 1
        for (int c = 0; c < 8; c++) {
            uint4 pvh[2], pvl[2];
            if (c < 7) {
                const uint4* gh_ = (const uint4*)g_hb_hi[pp];
                const uint4* gl_ = (const uint4*)g_hb_lo[pp];
#pragma unroll
                for (int s = 0; s < 2; s++) {
                    int e = tid + s * 512;
                    int r = e >> 4, q = e & 15;
                    pvh[s] = __ldcg(gh_ + r * 128 + (c + 1) * 16 + q);
                    pvl[s] = __ldcg(gl_ + r * 128 + (c + 1) * 16 + q);
                }
            }
            if (warp < 12) {
                const uint32_t abase = sb + RHS0 + (uint32_t)(c & 1) * RSTG;
#pragma unroll
                for (int kt = 0; kt < 8; kt++) {
                    uint32_t ah[4], al[4], bh[2], bl[2];
                    ldsm_x4(ah, abase + aoff + kt * 32);
                    ldsm_x4(al, abase + RHLO + aoff + kt * 32);
                    const uint32_t bo = boff + (uint32_t)(c * 128 + kt * 16) * 2;
                    ldsm_x2(bh, sb + RW_HI + bo);
                    ldsm_x2(bl, sb + RW_LO + bo);
                    mma16816(c0, ah, bh);
                    mma16816(c1, ah, bl);
                    mma16816(c2, al, bh);
                }
            }
            if (c < 7) {
                char* dst = rsm + RHS0 + ((c + 1) & 1) * RSTG;
#pragma unroll
                for (int s = 0; s < 2; s++) {
                    int e = tid + s * 512;
                    int r = e >> 4, q = e & 15;
                    *(uint4*)(dst + (r * 136 + q * 8) * 2) = pvh[s];
                    *(uint4*)(dst + RHLO + (r * 136 + q * 8) * 2) = pvl[s];
                }
                __syncthreads();
            }
        }

        // gh exchange (frag layout verified in R15)
        if (warp < 12) {
            const int g = lane >> 2, ct = lane & 3;
            float2 vA = {c0[0] + c1[0] + c2[0], c0[1] + c1[1] + c2[1]};
            float2 vB = {c0[2] + c1[2] + c2[2], c0[3] + c1[3] + c2[3]};
            *(float2*)(gh_s + (mt * 16 + g) * 26 + nt * 8 + ct * 2) = vA;
            *(float2*)(gh_s + (mt * 16 + g + 8) * 26 + nt * 8 + ct * 2) = vB;
        }
        __syncthreads();

        // gates: one (b, j) per thread
        {
            float sr = gh_s[gb * 26 + jl];
            float sz = gh_s[gb * 26 + 8 + jl];
            float sn = gh_s[gb * 26 + 16 + jl];
            float xr = ptr_ + sr + brr;
            float xz = ptz + sz + bzz;
            float gn = sn + bnn;
            float rg = 1.f / (1.f + __expf(-xr));
            float zg = 1.f / (1.f + __expf(-xz));
            float ng = tanhf(ptn + rg * gn);
            float hv = (1.f - zg) * ng + zg * phv;
            g_hbuf[pn][gb * DD + j] = hv;
            __nv_bfloat16 hh = __float2bfloat16(hv);
            __nv_bfloat16 hl = __float2bfloat16(hv - __bfloat162float(hh));
            g_hb_hi[pn][gb * DD + j] = hh;
            g_hb_lo[pn][gb * DD + j] = hl;
            const size_t hi_ = ((size_t)t * BB + gb) * DD + j;
            g_hs_hi[hi_] = hh;
            g_hs_lo[hi_] = hl;
        }
        __syncthreads();
        if (tid == 0) {
            __threadfence();
            atomicAdd(&g_cnt8[(cta & 7) * 32], 1u);
        }
    }
}

// ---------------- mma.sync bf16-split out-GEMM (unchanged from R15) ----------------
__global__ __launch_bounds__(256, 2) void out_mma(
    const float* __restrict__ bias, float* __restrict__ out)
{
    extern __shared__ __align__(16) __nv_bfloat16 osm[];
    const int tid = threadIdx.x;
    const int wid = tid >> 5;
    const int lane = tid & 31;
    const int wm = wid & 3;
    const int wn = wid >> 2;
    const int g = lane >> 2;
    const int ct = lane & 3;
    const int n0 = blockIdx.x * 128;
    const int m0 = blockIdx.y * 128;

    const __nv_bfloat16* srcs[4];
    {
        int r0 = (tid >> 1) & 127;
        int arow = m0 + r0; if (arow >= MTOT) arow = MTOT - 1;
        srcs[0] = g_hs_hi + (size_t)arow * DD;
        srcs[1] = g_hs_lo + (size_t)arow * DD;
        srcs[2] = g_lw_hi + (size_t)(n0 + r0) * DD;
        srcs[3] = g_lw_lo + (size_t)(n0 + r0) * DD;
    }

    float acc[2][8][4];
#pragma unroll
    for (int mt = 0; mt < 2; mt++)
#pragma unroll
        for (int nt = 0; nt < 8; nt++)
#pragma unroll
            for (int u = 0; u < 4; u++) acc[mt][nt][u] = 0.f;

#pragma unroll
    for (int i = 0; i < 4; i++) {
        int e = i * 256 + tid;
        int tile = e >> 8;
        int r = (e >> 1) & 127;
        int q = e & 1;
        uint4 v = *(const uint4*)(srcs[tile] + q * 8);
        *(uint4*)(osm + tile * OS_TILE + r * OS_STRIDE + q * 8) = v;
    }
    __syncthreads();

    const int fm = wm * 32 + g;
    const int fn = wn * 64 + g;

#pragma unroll 1
    for (int kc = 0; kc < 64; kc++) {
        const int cur = kc & 1;
        uint4 pre[4];
        if (kc < 63) {
            const int ko = (kc + 1) * 16;
#pragma unroll
            for (int i = 0; i < 4; i++) {
                int e = i * 256 + tid;
                int tile = e >> 8;
                int q = e & 1;
                pre[i] = *(const uint4*)(srcs[tile] + ko + q * 8);
            }
        }
        const __nv_bfloat16* st = osm + cur * OS_STAGE;
        uint32_t ah[2][4], al[2][4];
#pragma unroll
        for (int mt = 0; mt < 2; mt++) {
            int base = (fm + mt * 16) * OS_STRIDE + ct * 2;
            ah[mt][0] = *(const uint32_t*)(st + base);
            ah[mt][1] = *(const uint32_t*)(st + base + 8 * OS_STRIDE);
            ah[mt][2] = *(const uint32_t*)(st + base + 8);
            ah[mt][3] = *(const uint32_t*)(st + base + 8 * OS_STRIDE + 8);
            const __nv_bfloat16* stl = st + OS_TILE;
            al[mt][0] = *(const uint32_t*)(stl + base);
            al[mt][1] = *(const uint32_t*)(stl + base + 8 * OS_STRIDE);
            al[mt][2] = *(const uint32_t*)(stl + base + 8);
            al[mt][3] = *(const uint32_t*)(stl + base + 8 * OS_STRIDE + 8);
        }
#pragma unroll
        for (int nt = 0; nt < 8; nt++) {
            int base = (fn + nt * 8) * OS_STRIDE + ct * 2;
            uint32_t bh[2], bl[2];
            const __nv_bfloat16* sbh = st + 2 * OS_TILE;
            const __nv_bfloat16* sbl = st + 3 * OS_TILE;
            bh[0] = *(const uint32_t*)(sbh + base);
            bh[1] = *(const uint32_t*)(sbh + base + 8);
            bl[0] = *(const uint32_t*)(sbl + base);
            bl[1] = *(const uint32_t*)(sbl + base + 8);
#pragma unroll
            for (int mt = 0; mt < 2; mt++) {
                mma16816(acc[mt][nt], ah[mt], bh);
                mma16816(acc[mt][nt], ah[mt], bl);
                mma16816(acc[mt][nt], al[mt], bh);
            }
        }
        if (kc < 63) {
            __nv_bfloat16* dn = osm + (cur ^ 1) * OS_STAGE;
#pragma unroll
            for (int i = 0; i < 4; i++) {
                int e = i * 256 + tid;
                int tile = e >> 8;
                int r = (e >> 1) & 127;
                int q = e & 1;
                *(uint4*)(dn + tile * OS_TILE + r * OS_STRIDE + q * 8) = pre[i];
            }
            __syncthreads();
        }
    }

#pragma unroll
    for (int mt = 0; mt < 2; mt++) {
        const int mA = m0 + wm * 32 + mt * 16 + g;
        const int mB = mA + 8;
#pragma unroll
        for (int nt = 0; nt < 8; nt++) {
            const int col = n0 + wn * 64 + nt * 8 + ct * 2;
            float2 bv = *(const float2*)(bias + col);
            if (mA < MTOT) {
                float* o = out + ((size_t)(mA & 63) * TS + (mA >> 6)) * JJ + col;
                o[0] = acc[mt][nt][0] + bv.x;
                o[1] = acc[mt][nt][1] + bv.y;
            }
            if (mB < MTOT) {
                float* o = out + ((size_t)(mB & 63) * TS + (mB >> 6)) * JJ + col;
                o[0] = acc[mt][nt][2] + bv.x;
                o[1] = acc[mt][nt][3] + bv.y;
            }
        }
    }
}

// ---------------- launch ----------------
extern "C" void kernel_launch(void* const* d_in, const int* in_sizes, int n_in,
                              void* d_out, int out_size) {
    const int*   y     = (const int*)d_in[0];
    const float* embed = (const float*)d_in[1];
    const float* wih   = (const float*)d_in[2];
    const float* bih   = (const float*)d_in[3];
    const float* whh   = (const float*)d_in[4];
    const float* bhh   = (const float*)d_in[5];
    const float* lw    = (const float*)d_in[6];
    const float* lb    = (const float*)d_in[7];
    const float* h0    = (const float*)d_in[8];
    float* out = (float*)d_out;

    float* tbl = nullptr;
    cudaGetSymbolAddress((void**)&tbl, g_table);

    static bool attr_done = false;
    if (!attr_done) {
        cudaFuncSetAttribute(recurrent, cudaFuncAttributeMaxDynamicSharedMemorySize, REC_SMEM);
        cudaFuncSetAttribute(out_mma, cudaFuncAttributeMaxDynamicSharedMemorySize, OS_SMEM_BYTES);
        attr_done = true;
    }

    // 1) vocab table: table[v][0:3072] = embed[v]·W_ih^T + b_ih
    gemm_nt<<<dim3(G3 / 128, VV / 64), 256>>>(embed, wih, bih, tbl, G3);
    // 2) linear_w -> bf16 (hi, lo)
    convert_lw<<<(JJ * DD + 255) / 256, 256>>>(lw);
    // 3) persistent recurrence over 513 steps (HMMA step-GEMM)
    recurrent<<<NCTA, THREADS, REC_SMEM>>>(whh, bhh, y, h0);
    // 4) tensor-core (HMMA) out-GEMM with remap epilogue
    out_mma<<<dim3(JJ / 128, (MTOT + 127) / 128), 256, OS_SMEM_BYTES>>>(lb, out);
}